// round 5
// baseline (speedup 1.0000x reference)
#include <cuda_runtime.h>
#include <math.h>

#define ATOMS 48
#define CAP   48          // per-species bucket capacity
#define GMAX  192         // max groups = 4 * max neighbors
#define BLK   128
#define GBS   193         // gbuf stride (conflict-free padding)

// cos/sin of SHF_Z[z] = (2z+1)*pi/16
__device__ __constant__ float COSZ[8] = {
     0.98078528040323044913f,  0.83146961230254523708f,
     0.55557023301960222474f,  0.19509032201612826785f,
    -0.19509032201612826785f, -0.55557023301960222474f,
    -0.83146961230254523708f, -0.98078528040323044913f };
__device__ __constant__ float SINZ[8] = {
     0.19509032201612826785f,  0.55557023301960222474f,
     0.83146961230254523708f,  0.98078528040323044913f,
     0.98078528040323044913f,  0.83146961230254523708f,
     0.55557023301960222474f,  0.19509032201612826785f };

// PAIR_IDX for 4 species (upper-triangular enumeration, symmetric)
__device__ __constant__ int PAIRT[4][4] = {
    {0,1,2,3},{1,4,5,6},{2,5,7,8},{3,6,8,9} };

// ---- packed fp32x2 helpers (sm_103a FFMA2/FMUL2 — PTX-only) ----
typedef unsigned long long u64;
__device__ __forceinline__ u64 pack2(float lo, float hi) {
    u64 r; asm("mov.b64 %0,{%1,%2};" : "=l"(r) : "f"(lo), "f"(hi)); return r;
}
__device__ __forceinline__ void unpack2(u64 v, float& lo, float& hi) {
    asm("mov.b64 {%0,%1},%2;" : "=f"(lo), "=f"(hi) : "l"(v));
}
__device__ __forceinline__ u64 fma2(u64 a, u64 b, u64 c) {
    u64 d; asm("fma.rn.f32x2 %0,%1,%2,%3;" : "=l"(d) : "l"(a), "l"(b), "l"(c)); return d;
}
__device__ __forceinline__ u64 mul2(u64 a, u64 b) {
    u64 d; asm("mul.rn.f32x2 %0,%1,%2;" : "=l"(d) : "l"(a), "l"(b)); return d;
}

__global__ void __launch_bounds__(BLK)
aev_kernel(const int* __restrict__ species, const float* __restrict__ coords,
           float* __restrict__ aev_out, float* __restrict__ sp_out)
{
    const int i = blockIdx.x;          // atom within batch
    const int b = blockIdx.y;          // batch
    const int A = gridDim.x;           // 48
    const int tid = threadIdx.x;

    __shared__ float cx[ATOMS], cy[ATOMS], cz[ATOMS];
    __shared__ int   sp[ATOMS];
    __shared__ float4 bvec[GMAX];      // (vx, vy, vz, d)
    __shared__ float2 bsc[GMAX];       // (1/d, fc_a)
    __shared__ float2 rpak[GMAX];      // (d, 0.25*fc_r)
    __shared__ int   cnt[4], rcnt[4];
    __shared__ int   jlist[ATOMS];     // packed: slot | (s_j << 8)
    __shared__ int   Mtot;
    __shared__ int   gcnt[10];
    __shared__ int   glistP[10][CAP];  // groups per pair-class
    __shared__ float gbuf[32 * GBS];   // [feature][group] scratch

    const float* cb = coords + (size_t)b * A * 3;
    if (tid < A) {
        cx[tid] = cb[tid*3 + 0];
        cy[tid] = cb[tid*3 + 1];
        cz[tid] = cb[tid*3 + 2];
        sp[tid] = species[b*A + tid];
    }
    if (tid < 4)  { cnt[tid] = 0; rcnt[tid] = 0; }
    if (tid == 4) Mtot = 0;
    if (tid >= 8 && tid < 18) gcnt[tid - 8] = 0;
    __syncthreads();

    const float xi = cx[i], yi = cy[i], zi = cz[i];

    // ---- phase 1: distances, bucketed neighbor lists ----
    if (tid < A && tid != i) {
        float dx = cx[tid] - xi;
        float dy = cy[tid] - yi;
        float dz = cz[tid] - zi;
        float d  = sqrtf(dx*dx + dy*dy + dz*dz);
        int   s  = sp[tid];
        if (d <= 5.2f) {
            float fcr = 0.5f * cospif(d / 5.2f) + 0.5f;
            int m = atomicAdd(&rcnt[s], 1);
            rpak[s*CAP + m] = make_float2(d, 0.25f * fcr);
        }
        if (d <= 3.5f) {
            float fca = 0.5f * cospif(d / 3.5f) + 0.5f;
            int m    = atomicAdd(&cnt[s], 1);
            int slot = s*CAP + m;
            bvec[slot] = make_float4(dx, dy, dz, d);
            bsc[slot]  = make_float2(1.0f / d, fca);
            int pos = atomicAdd(&Mtot, 1);
            jlist[pos] = slot | (s << 8);
        }
    }
    __syncthreads();

    // ---- phase 2: angular groups (j, species_k), packed register accumulate ----
    // Ordered-pair sum with weight fc_j*fc_k == reference's unordered sum
    // with weight 2*fc_j*fc_k (integrand symmetric in j,k).
    const u64 half2 = pack2(0.5f, 0.5f);
    u64 cz2[4], sz2[4];
    #pragma unroll
    for (int zp = 0; zp < 4; zp++) {
        cz2[zp] = pack2(COSZ[2*zp], COSZ[2*zp+1]);
        sz2[zp] = pack2(SINZ[2*zp], SINZ[2*zp+1]);
    }
    const float K1 = __expf(-6.76f);   // exp step for the f2 recurrence

    const int M = Mtot;
    const int G = 4 * M;
    for (int g = tid; g < G; g += BLK) {
        const int jid   = jlist[g >> 2];
        const int jslot = jid & 255;
        const int sj    = jid >> 8;
        const int sk    = g & 3;

        const float4 jv = bvec[jslot];
        const float2 js = bsc[jslot];

        u64 acc2[16];                  // [a][zpair] packed fp32x2
        #pragma unroll
        for (int q = 0; q < 16; q++) acc2[q] = 0ull;

        const int n    = cnt[sk];
        const int base = sk * CAP;
        for (int m = 0; m < n; m++) {
            const int kslot = base + m;
            if (kslot == jslot) continue;
            float4 kv = bvec[kslot];
            float2 ks = bsc[kslot];
            float dot = jv.x*kv.x + jv.y*kv.y + jv.z*kv.z;
            float ct  = 0.95f * dot * js.x * ks.x;        // |ct| <= 0.95
            float st  = sqrtf(fmaxf(1.0f - ct*ct, 0.0f));
            float avg = 0.5f * (jv.w + kv.w);
            float w   = js.y * ks.y;

            // f2v[a] = w*exp(-8*(u-0.65a)^2) via exact geometric recurrence:
            // 2 MUFU instead of 4.
            float u  = avg - 0.9f;
            float f0 = w * __expf(-8.0f * u * u);
            float r  = __expf(fmaf(10.4f, u, -3.38f));
            float f1v = f0 * r;
            float r2  = r * K1;
            float f2v = f1v * r2;
            float r3  = r2 * K1;
            float f3v = f2v * r3;

            u64 ct2 = pack2(ct, ct);
            u64 st2 = pack2(st, st);
            u64 fp0 = pack2(f0,  f0);
            u64 fp1 = pack2(f1v, f1v);
            u64 fp2 = pack2(f2v, f2v);
            u64 fp3 = pack2(f3v, f3v);

            #pragma unroll
            for (int zp = 0; zp < 4; zp++) {
                // c = ct*cos(shfz) + st*sin(shfz) == cos(acos(ct)-shfz)
                u64 c2  = fma2(ct2, cz2[zp], mul2(st2, sz2[zp]));
                u64 b1  = fma2(c2, half2, half2);          // (1+c)/2
                u64 b2  = mul2(b1, b1);
                u64 b4  = mul2(b2, b2);
                u64 b8  = mul2(b4, b4);
                u64 b16 = mul2(b8, b8);
                u64 f1p = mul2(b16, b16);                  // b1^32
                acc2[0*4 + zp] = fma2(fp0, f1p, acc2[0*4 + zp]);
                acc2[1*4 + zp] = fma2(fp1, f1p, acc2[1*4 + zp]);
                acc2[2*4 + zp] = fma2(fp2, f1p, acc2[2*4 + zp]);
                acc2[3*4 + zp] = fma2(fp3, f1p, acc2[3*4 + zp]);
            }
        }

        const int p = PAIRT[sj][sk];
        int mm = atomicAdd(&gcnt[p], 1);
        glistP[p][mm] = g;
        #pragma unroll
        for (int a = 0; a < 4; a++) {
            #pragma unroll
            for (int zp = 0; zp < 4; zp++) {
                float lo, hi;
                unpack2(acc2[a*4 + zp], lo, hi);
                gbuf[(a*8 + 2*zp    ) * GBS + g] = lo;     // conflict-free
                gbuf[(a*8 + 2*zp + 1) * GBS + g] = hi;
            }
        }
    }
    __syncthreads();

    // ---- phase 3: feature-per-thread reductions, direct output ----
    float* o = aev_out + (size_t)(b * A + i) * 384;

    // radial: feature (s, r); 16-lane groups share species s
    if (tid < 64) {
        const int s = tid >> 4;
        const int r = tid & 15;
        const float shf = 0.9f + 0.26875f * (float)r;
        const int n = rcnt[s];
        float acc = 0.0f;
        for (int m = 0; m < n; m++) {
            float2 v = rpak[s*CAP + m];        // broadcast within 16-lane group
            float u = v.x - shf;
            acc += v.y * __expf(-16.0f * u * u);
        }
        o[tid] = acc;
    }

    // angular: feature (p, q); each 32-lane warp-chunk = one class p
    #pragma unroll
    for (int base = 0; base < 384; base += BLK) {
        int f = base + tid;
        if (f < 320) {
            const int p = f >> 5;
            const int q = f & 31;
            const int n = gcnt[p];
            float acc = 0.0f;
            for (int m = 0; m < n; m++) {
                int g = glistP[p][m];          // broadcast
                acc += gbuf[q * GBS + g];      // conflict-free: lanes->consec q
            }
            o[64 + f] = acc;
        }
    }

    if (sp_out != nullptr && tid == 0)
        sp_out[b * A + i] = (float)sp[i];
}

extern "C" void kernel_launch(void* const* d_in, const int* in_sizes, int n_in,
                              void* d_out, int out_size)
{
    const int*   species = (const int*)d_in[0];
    const float* coords  = (const float*)d_in[1];

    const int BA = in_sizes[0];     // B*A
    const int A  = ATOMS;           // 48 per reference
    const int B  = BA / A;
    const int aev_total = BA * 384;

    float* out    = (float*)d_out;
    float* sp_out = nullptr;
    float* aev    = out;
    if (out_size >= aev_total + BA) {   // tuple output: species first, then aevs
        sp_out = out;
        aev    = out + BA;
    }

    dim3 grid(A, B);
    aev_kernel<<<grid, BLK>>>(species, coords, aev, sp_out);
}

// round 6
// speedup vs baseline: 1.0911x; 1.0911x over previous
#include <cuda_runtime.h>
#include <math.h>

#define ATOMS 48
#define CAP   48          // per-species bucket capacity
#define GMAX  192         // max groups = 4 * max neighbors
#define BLK   128
#define GBS   193         // gbuf stride (conflict-free padding)

// cos/sin of SHF_Z[z] = (2z+1)*pi/16
__device__ __constant__ float COSZ[8] = {
     0.98078528040323044913f,  0.83146961230254523708f,
     0.55557023301960222474f,  0.19509032201612826785f,
    -0.19509032201612826785f, -0.55557023301960222474f,
    -0.83146961230254523708f, -0.98078528040323044913f };
__device__ __constant__ float SINZ[8] = {
     0.19509032201612826785f,  0.55557023301960222474f,
     0.83146961230254523708f,  0.98078528040323044913f,
     0.98078528040323044913f,  0.83146961230254523708f,
     0.55557023301960222474f,  0.19509032201612826785f };

// PAIR_IDX for 4 species (upper-triangular enumeration, symmetric)
__device__ __constant__ int PAIRT[4][4] = {
    {0,1,2,3},{1,4,5,6},{2,5,7,8},{3,6,8,9} };

__global__ void __launch_bounds__(BLK)
aev_kernel(const int* __restrict__ species, const float* __restrict__ coords,
           float* __restrict__ aev_out, float* __restrict__ sp_out)
{
    const int i = blockIdx.x;          // atom within batch
    const int b = blockIdx.y;          // batch
    const int A = gridDim.x;           // 48
    const int tid = threadIdx.x;

    __shared__ float cx[ATOMS], cy[ATOMS], cz[ATOMS];
    __shared__ int   sp[ATOMS];
    __shared__ float4 bvec[GMAX];      // (vx, vy, vz, d)
    __shared__ float2 bsc[GMAX];       // (1/d, fc_a)
    __shared__ float2 rpak[GMAX];      // (d, 0.25*fc_r)
    __shared__ int   cnt[4], rcnt[4];
    __shared__ int   jlist[ATOMS];     // packed: slot | (s_j << 8)
    __shared__ int   Mtot;
    __shared__ int   gcnt[10];
    __shared__ int   glistP[10][CAP];  // groups per pair-class
    __shared__ float gbuf[32 * GBS];   // [feature][group] scratch

    const float* cb = coords + (size_t)b * A * 3;
    if (tid < A) {
        cx[tid] = cb[tid*3 + 0];
        cy[tid] = cb[tid*3 + 1];
        cz[tid] = cb[tid*3 + 2];
        sp[tid] = species[b*A + tid];
    }
    if (tid < 4)  { cnt[tid] = 0; rcnt[tid] = 0; }
    if (tid == 4) Mtot = 0;
    if (tid >= 8 && tid < 18) gcnt[tid - 8] = 0;
    __syncthreads();

    const float xi = cx[i], yi = cy[i], zi = cz[i];

    // ---- phase 1: distances, bucketed neighbor lists ----
    if (tid < A && tid != i) {
        float dx = cx[tid] - xi;
        float dy = cy[tid] - yi;
        float dz = cz[tid] - zi;
        float d  = sqrtf(dx*dx + dy*dy + dz*dz);
        int   s  = sp[tid];
        if (d <= 5.2f) {
            float fcr = 0.5f * cospif(d / 5.2f) + 0.5f;
            int m = atomicAdd(&rcnt[s], 1);
            rpak[s*CAP + m] = make_float2(d, 0.25f * fcr);
        }
        if (d <= 3.5f) {
            float fca = 0.5f * cospif(d / 3.5f) + 0.5f;
            int m    = atomicAdd(&cnt[s], 1);
            int slot = s*CAP + m;
            bvec[slot] = make_float4(dx, dy, dz, d);
            bsc[slot]  = make_float2(1.0f / d, fca);
            int pos = atomicAdd(&Mtot, 1);
            jlist[pos] = slot | (s << 8);
        }
    }
    __syncthreads();

    // ---- phase 2: angular groups, sk-major ordering (divergence-free) ----
    // g = sk*M + jidx  =>  a warp's lanes share sk, hence share the inner
    // trip count cnt[sk].  Ordered-pair sum with weight fc_j*fc_k equals the
    // reference's unordered sum with weight 2*fc_j*fc_k (symmetric in j,k).
    const float K1 = __expf(-6.76f);   // exp step for the f2 recurrence
    const int M = Mtot;
    const int G = 4 * M;
    for (int g = tid; g < G; g += BLK) {
        const int sk    = g / M;
        const int jidx  = g - sk * M;
        const int jid   = jlist[jidx];
        const int jslot = jid & 255;
        const int sj    = jid >> 8;

        const float4 jv = bvec[jslot];
        const float2 js = bsc[jslot];

        float acc[32];
        #pragma unroll
        for (int q = 0; q < 32; q++) acc[q] = 0.0f;

        const int n    = cnt[sk];
        const int base = sk * CAP;
        #pragma unroll 2
        for (int m = 0; m < n; m++) {
            const int kslot = base + m;
            float4 kv = bvec[kslot];
            float2 ks = bsc[kslot];
            float dot = jv.x*kv.x + jv.y*kv.y + jv.z*kv.z;
            float ct  = 0.95f * dot * js.x * ks.x;        // |ct| <= 0.95
            float st  = sqrtf(fmaxf(1.0f - ct*ct, 0.0f));
            float avg = 0.5f * (jv.w + kv.w);
            float w   = (kslot == jslot) ? 0.0f : js.y * ks.y;

            // f2v[a] = w*exp(-8*(u-0.65a)^2) via exact geometric recurrence
            float u   = avg - 0.9f;
            float f0  = w * __expf(-8.0f * u * u);
            float r   = __expf(fmaf(10.4f, u, -3.38f));
            float f1v = f0 * r;
            float r2  = r * K1;
            float f2v = f1v * r2;
            float r3  = r2 * K1;
            float f3v = f2v * r3;

            #pragma unroll
            for (int z = 0; z < 8; z++) {
                float c   = ct * COSZ[z] + st * SINZ[z];  // cos(acos(ct)-shfz)
                float b1  = 0.5f + 0.5f * c;
                float b2  = b1 * b1;
                float b4  = b2 * b2;
                float b8  = b4 * b4;
                float b16 = b8 * b8;
                float f1  = b16 * b16;                    // b1^32
                acc[0*8 + z] += f0  * f1;
                acc[1*8 + z] += f1v * f1;
                acc[2*8 + z] += f2v * f1;
                acc[3*8 + z] += f3v * f1;
            }
        }

        const int p = PAIRT[sj][sk];
        int mm = atomicAdd(&gcnt[p], 1);
        glistP[p][mm] = g;
        #pragma unroll
        for (int q = 0; q < 32; q++)
            gbuf[q * GBS + g] = acc[q];        // conflict-free: lanes->consec g
    }
    __syncthreads();

    // ---- phase 3: feature-per-thread reductions, direct output ----
    float* o = aev_out + (size_t)(b * A + i) * 384;

    // radial: feature (s, r); 16-lane groups share species s
    if (tid < 64) {
        const int s = tid >> 4;
        const int r = tid & 15;
        const float shf = 0.9f + 0.26875f * (float)r;
        const int n = rcnt[s];
        float acc = 0.0f;
        for (int m = 0; m < n; m++) {
            float2 v = rpak[s*CAP + m];        // broadcast within 16-lane group
            float u = v.x - shf;
            acc += v.y * __expf(-16.0f * u * u);
        }
        o[tid] = acc;
    }

    // angular: feature (p, q); each 32-lane warp-chunk = one class p
    #pragma unroll
    for (int base = 0; base < 384; base += BLK) {
        int f = base + tid;
        if (f < 320) {
            const int p = f >> 5;
            const int q = f & 31;
            const int n = gcnt[p];
            float acc = 0.0f;
            for (int m = 0; m < n; m++) {
                int g = glistP[p][m];          // broadcast
                acc += gbuf[q * GBS + g];      // conflict-free: lanes->consec q
            }
            o[64 + f] = acc;
        }
    }

    if (sp_out != nullptr && tid == 0)
        sp_out[b * A + i] = (float)sp[i];
}

extern "C" void kernel_launch(void* const* d_in, const int* in_sizes, int n_in,
                              void* d_out, int out_size)
{
    const int*   species = (const int*)d_in[0];
    const float* coords  = (const float*)d_in[1];

    const int BA = in_sizes[0];     // B*A
    const int A  = ATOMS;           // 48 per reference
    const int B  = BA / A;
    const int aev_total = BA * 384;

    float* out    = (float*)d_out;
    float* sp_out = nullptr;
    float* aev    = out;
    if (out_size >= aev_total + BA) {   // tuple output: species first, then aevs
        sp_out = out;
        aev    = out + BA;
    }

    dim3 grid(A, B);
    aev_kernel<<<grid, BLK>>>(species, coords, aev, sp_out);
}